// round 9
// baseline (speedup 1.0000x reference)
#include <cuda_runtime.h>
#include <cuda_fp16.h>

#define N_NODES 50000
#define N_EDGES 1600000
#define NCLS    48
#define NH2     24            // active half2 per row
#define ROWP    32            // padded half2 per row (128B rows)
#define NSTEP   10
#define SCAN_B  1024
#define CHUNK   49            // ceil(50000/1024)
#define PERS_BLOCKS 1216      // persistent grid for step1 only

// ---------------- device scratch (static, no runtime allocation) -------------
__device__ float   g_deg[N_NODES];
__device__ int     g_cnt[N_NODES];
__device__ int     g_off[N_NODES + 1];
__device__ int     g_cur[N_NODES];
__device__ __align__(16) unsigned g_epk[N_EDGES];    // (src<<16 | w_half_bits), CSR order
__device__ __align__(16) unsigned g_e1[N_EDGES];     // (cls<<16 | w_half_bits), CSR order
__device__ __half2 g_hh[2][(size_t)N_NODES * ROWP];  // fp16 feature buffers, 128B rows

static __device__ __forceinline__ __half2 wrep(unsigned v) {
    unsigned r = __byte_perm(v, v, 0x1010);
    __half2 h; *reinterpret_cast<unsigned*>(&h) = r; return h;
}
static __device__ __forceinline__ unsigned srcidx(unsigned v) { return v >> 16; }

// ---------------- preprocessing ------------------------------------------------
__global__ void deg_kernel(const int* __restrict__ row, const int* __restrict__ col,
                           const float* __restrict__ attr) {
    int e = blockIdx.x * blockDim.x + threadIdx.x;
    if (e < N_EDGES) {
        atomicAdd(&g_deg[row[e]], attr[e]);
        atomicAdd(&g_cnt[col[e]], 1);
    }
}

// single-block exclusive scan of g_cnt -> g_off / g_cur (3-phase)
__global__ void scan_kernel() {
    __shared__ int sh[SCAN_B];
    int tid = threadIdx.x;
    int base = tid * CHUNK;

    int sum = 0;
    #pragma unroll 4
    for (int k = 0; k < CHUNK; k++) {
        int i = base + k;
        if (i < N_NODES) sum += g_cnt[i];
    }
    sh[tid] = sum;
    __syncthreads();
    for (int d = 1; d < SCAN_B; d <<= 1) {
        int t = (tid >= d) ? sh[tid - d] : 0;
        __syncthreads();
        sh[tid] += t;
        __syncthreads();
    }
    int run = sh[tid] - sum;
    #pragma unroll 4
    for (int k = 0; k < CHUNK; k++) {
        int i = base + k;
        if (i < N_NODES) {
            g_off[i] = run;
            g_cur[i] = run;
            run += g_cnt[i];
        }
    }
    if (tid == 0) g_off[N_NODES] = N_EDGES;
}

__global__ void fill_kernel(const int* __restrict__ row, const int* __restrict__ col,
                            const float* __restrict__ attr, const int* __restrict__ target) {
    int e = blockIdx.x * blockDim.x + threadIdx.x;
    if (e < N_EDGES) {
        int r = row[e];
        int c = col[e];
        float w = attr[e] / fmaxf(g_deg[r], 1e-12f);
        unsigned wb = (unsigned)__half_as_ushort(__float2half_rn(w));
        int p = atomicAdd(&g_cur[c], 1);
        g_epk[p] = ((unsigned)r << 16) | wb;
        g_e1[p]  = ((unsigned)target[r] << 16) | wb;   // 200KB table, L2-hit
    }
}

// ---------------- step 0: one-hot propagation via per-warp smem histogram ------
__global__ void __launch_bounds__(256)
step1_kernel(const float* __restrict__ Wm, float* __restrict__ out) {
    __shared__ float hist[8][NCLS];
    int wip  = threadIdx.x >> 5;
    int lane = threadIdx.x & 31;
    float* h = hist[wip];

    int gw = (blockIdx.x * blockDim.x + threadIdx.x) >> 5;
    int nw = (gridDim.x * blockDim.x) >> 5;

    __half2* __restrict__ hout = g_hh[1];

    for (int n = gw; n < N_NODES; n += nw) {
        if (lane < NH2) { h[lane] = 0.f; h[lane + NH2] = 0.f; }
        __syncwarp();

        int beg = g_off[n];
        int end = g_off[n + 1];
        for (int j = beg + lane; j < end; j += 32) {
            unsigned v = g_e1[j];
            float w = __half2float(__ushort_as_half((unsigned short)(v & 0xffffu)));
            atomicAdd(&h[v >> 16], w);
        }
        __syncwarp();

        if (lane < NH2) {
            float accx = h[2 * lane];
            float accy = h[2 * lane + 1];
            hout[(size_t)n * ROWP + lane] = __floats2half2_rn(accx, accy);
            float2 o;
            o.x = accx * Wm[(2 * lane) * NSTEP];       // s = 0
            o.y = accy * Wm[(2 * lane + 1) * NSTEP];
            float2* op = (float2*)(out + (size_t)n * NCLS) + lane;
            *op = o;                                    // overwrite poisoned out
        }
        __syncwarp();
    }
}

// ---------------- steps 1..9: one warp per node, pipelined meta lookahead -----
__global__ void __launch_bounds__(256)
gather_kernel(const float* __restrict__ Wm, float* __restrict__ out, int s) {
    int gwarp = (blockIdx.x * blockDim.x + threadIdx.x) >> 5;
    int lane  = threadIdx.x & 31;
    if (gwarp >= N_NODES) return;

    const __half2* __restrict__ hin  = g_hh[s & 1] + lane;   // lane-offset base
    __half2*       __restrict__ hout = g_hh[(s & 1) ^ 1];

    int beg = g_off[gwarp];
    int end = g_off[gwarp + 1];
    bool act = (lane < NH2);

    float accx = 0.f, accy = 0.f;
    __half2 hacc = __floats2half2_rn(0.f, 0.f);

    int j = beg;
    // peel to 16B alignment of the packed metadata
    for (; j < end && (j & 3); j++) {
        unsigned v = g_epk[j];
        if (act) {
            __half2 x = hin[srcidx(v) << 5];
            hacc = __hfma2(wrep(v), x, hacc);
        }
    }

    if (j + 8 <= end) {
        uint4 m0 = __ldcs(reinterpret_cast<const uint4*>(g_epk + j));
        uint4 m1 = __ldcs(reinterpret_cast<const uint4*>(g_epk + j + 4));
        for (;;) {
            bool more = (j + 16 <= end);
            uint4 n0, n1;
            if (more) {          // lookahead: overlap next meta with this iter's rows
                n0 = __ldcs(reinterpret_cast<const uint4*>(g_epk + j + 8));
                n1 = __ldcs(reinterpret_cast<const uint4*>(g_epk + j + 12));
            }
            if (act) {
                __half2 x0 = hin[srcidx(m0.x) << 5];
                __half2 x1 = hin[srcidx(m0.y) << 5];
                __half2 x2 = hin[srcidx(m0.z) << 5];
                __half2 x3 = hin[srcidx(m0.w) << 5];
                __half2 x4 = hin[srcidx(m1.x) << 5];
                __half2 x5 = hin[srcidx(m1.y) << 5];
                __half2 x6 = hin[srcidx(m1.z) << 5];
                __half2 x7 = hin[srcidx(m1.w) << 5];
                __half2 p0 = __hmul2(wrep(m0.x), x0);
                __half2 p1 = __hmul2(wrep(m0.y), x1);
                p0 = __hfma2(wrep(m0.z), x2, p0);
                p1 = __hfma2(wrep(m0.w), x3, p1);
                p0 = __hfma2(wrep(m1.x), x4, p0);
                p1 = __hfma2(wrep(m1.y), x5, p1);
                p0 = __hfma2(wrep(m1.z), x6, p0);
                p1 = __hfma2(wrep(m1.w), x7, p1);
                float2 f = __half22float2(__hadd2(p0, p1));
                accx += f.x;
                accy += f.y;
            }
            j += 8;
            if (!more) break;
            m0 = n0; m1 = n1;
        }
    }
    for (; j < end; j++) {
        unsigned v = g_epk[j];
        if (act) {
            __half2 x = hin[srcidx(v) << 5];
            hacc = __hfma2(wrep(v), x, hacc);
        }
    }

    if (act) {
        float2 fr = __half22float2(hacc);
        accx += fr.x;
        accy += fr.y;

        hout[(size_t)gwarp * ROWP + lane] = __floats2half2_rn(accx, accy);

        float2 o;
        o.x = accx * Wm[(2 * lane) * NSTEP + s];
        o.y = accy * Wm[(2 * lane + 1) * NSTEP + s];
        float2* op = (float2*)(out + (size_t)gwarp * NCLS) + lane;
        float2 p = *op; o.x += p.x; o.y += p.y;
        *op = o;
    }
}

// ---------------- launch ------------------------------------------------------
extern "C" void kernel_launch(void* const* d_in, const int* in_sizes, int n_in,
                              void* d_out, int out_size) {
    const int*   ei     = (const int*)d_in[0];     // [2, E]
    const int*   row    = ei;
    const int*   col    = ei + N_EDGES;
    const float* attr   = (const float*)d_in[1];   // [E]
    const int*   target = (const int*)d_in[2];     // [N]
    const float* Wm     = (const float*)d_in[3];   // [C, S]
    float*       out    = (float*)d_out;           // [N, C]

    void* p_deg = nullptr; void* p_cnt = nullptr;
    cudaGetSymbolAddress(&p_deg, g_deg);
    cudaGetSymbolAddress(&p_cnt, g_cnt);
    cudaMemsetAsync(p_deg, 0, N_NODES * sizeof(float));
    cudaMemsetAsync(p_cnt, 0, N_NODES * sizeof(int));

    const int TB = 256;
    int nblk_edges = (N_EDGES + TB - 1) / TB;
    int nblk_warp  = (N_NODES + 7) / 8;    // 8 warps/block, 1 node/warp

    deg_kernel<<<nblk_edges, TB>>>(row, col, attr);            // launch 1
    scan_kernel<<<1, SCAN_B>>>();                              // launch 2
    fill_kernel<<<nblk_edges, TB>>>(row, col, attr, target);   // launch 3

    step1_kernel<<<PERS_BLOCKS, TB>>>(Wm, out);                // launch 4 (s=0)
    for (int s = 1; s < NSTEP; s++) {
        gather_kernel<<<nblk_warp, TB>>>(Wm, out, s);          // launches 5..13
    }
}

// round 10
// speedup vs baseline: 1.2830x; 1.2830x over previous
#include <cuda_runtime.h>
#include <cuda_fp16.h>

#define N_NODES 50000
#define N_EDGES 1600000
#define NCLS    48
#define NH2     24            // active half2 per row
#define ROWP    32            // padded half2 per row (128B rows)
#define NSTEP   10
#define SCAN_B  1024
#define CHUNK   49            // ceil(50000/1024)
#define PERS_BLOCKS 1216      // persistent grid for step1 only

// ---------------- device scratch (static, no runtime allocation) -------------
__device__ float   g_deg[N_NODES];
__device__ int     g_cnt[N_NODES];
__device__ int     g_off[N_NODES + 1];
__device__ int     g_cur[N_NODES];
__device__ __align__(16) unsigned g_epk[N_EDGES];    // (src<<16 | w_half_bits), CSR order
__device__ __half2 g_hh[2][(size_t)N_NODES * ROWP];  // fp16 feature buffers, 128B rows

static __device__ __forceinline__ __half2 wrep(unsigned v) {
    unsigned r = __byte_perm(v, v, 0x1010);
    __half2 h; *reinterpret_cast<unsigned*>(&h) = r; return h;
}
static __device__ __forceinline__ unsigned srcidx(unsigned v) { return v >> 16; }

// ---------------- preprocessing ------------------------------------------------
__global__ void deg_kernel(const int* __restrict__ row, const int* __restrict__ col,
                           const float* __restrict__ attr) {
    int e = blockIdx.x * blockDim.x + threadIdx.x;
    if (e < N_EDGES) {
        atomicAdd(&g_deg[row[e]], attr[e]);
        atomicAdd(&g_cnt[col[e]], 1);
    }
}

// single-block exclusive scan of g_cnt -> g_off / g_cur (3-phase)
__global__ void scan_kernel() {
    __shared__ int sh[SCAN_B];
    int tid = threadIdx.x;
    int base = tid * CHUNK;

    int sum = 0;
    #pragma unroll 4
    for (int k = 0; k < CHUNK; k++) {
        int i = base + k;
        if (i < N_NODES) sum += g_cnt[i];
    }
    sh[tid] = sum;
    __syncthreads();
    for (int d = 1; d < SCAN_B; d <<= 1) {
        int t = (tid >= d) ? sh[tid - d] : 0;
        __syncthreads();
        sh[tid] += t;
        __syncthreads();
    }
    int run = sh[tid] - sum;
    #pragma unroll 4
    for (int k = 0; k < CHUNK; k++) {
        int i = base + k;
        if (i < N_NODES) {
            g_off[i] = run;
            g_cur[i] = run;
            run += g_cnt[i];
        }
    }
    if (tid == 0) g_off[N_NODES] = N_EDGES;
}

__global__ void fill_kernel(const int* __restrict__ row, const int* __restrict__ col,
                            const float* __restrict__ attr) {
    int e = blockIdx.x * blockDim.x + threadIdx.x;
    if (e < N_EDGES) {
        int r = row[e];
        int c = col[e];
        float w = attr[e] / fmaxf(g_deg[r], 1e-12f);
        unsigned wb = (unsigned)__half_as_ushort(__float2half_rn(w));
        int p = atomicAdd(&g_cur[c], 1);
        g_epk[p] = ((unsigned)r << 16) | wb;
    }
}

// ---------------- step 0: one-hot propagation via per-warp smem histogram ------
// class = target[src] looked up on the fly (200KB table, cache-resident)
__global__ void __launch_bounds__(256)
step1_kernel(const int* __restrict__ target, const float* __restrict__ Wm,
             float* __restrict__ out) {
    __shared__ float hist[8][NCLS];
    int wip  = threadIdx.x >> 5;
    int lane = threadIdx.x & 31;
    float* h = hist[wip];

    int gw = (blockIdx.x * blockDim.x + threadIdx.x) >> 5;
    int nw = (gridDim.x * blockDim.x) >> 5;

    __half2* __restrict__ hout = g_hh[1];

    for (int n = gw; n < N_NODES; n += nw) {
        if (lane < NH2) { h[lane] = 0.f; h[lane + NH2] = 0.f; }
        __syncwarp();

        int beg = g_off[n];
        int end = g_off[n + 1];
        for (int j = beg + lane; j < end; j += 32) {
            unsigned v = g_epk[j];
            int c = target[v >> 16];
            float w = __half2float(__ushort_as_half((unsigned short)(v & 0xffffu)));
            atomicAdd(&h[c], w);
        }
        __syncwarp();

        if (lane < NH2) {
            float accx = h[2 * lane];
            float accy = h[2 * lane + 1];
            hout[(size_t)n * ROWP + lane] = __floats2half2_rn(accx, accy);
            float2 o;
            o.x = accx * Wm[(2 * lane) * NSTEP];       // s = 0
            o.y = accy * Wm[(2 * lane + 1) * NSTEP];
            float2* op = (float2*)(out + (size_t)n * NCLS) + lane;
            *op = o;                                    // overwrite poisoned out
        }
        __syncwarp();
    }
}

// ---------------- steps 1..9: one warp per node, packed 4B edge metadata ------
__global__ void __launch_bounds__(256)
gather_kernel(const float* __restrict__ Wm, float* __restrict__ out, int s) {
    int gwarp = (blockIdx.x * blockDim.x + threadIdx.x) >> 5;
    int lane  = threadIdx.x & 31;
    if (gwarp >= N_NODES) return;

    const __half2* __restrict__ hin  = g_hh[s & 1] + lane;   // lane-offset base
    __half2*       __restrict__ hout = g_hh[(s & 1) ^ 1];

    int beg = g_off[gwarp];
    int end = g_off[gwarp + 1];
    bool act = (lane < NH2);

    float accx = 0.f, accy = 0.f;
    __half2 hacc = __floats2half2_rn(0.f, 0.f);

    int j = beg;
    // peel to 16B alignment of the packed metadata
    for (; j < end && (j & 3); j++) {
        unsigned v = g_epk[j];
        if (act) {
            __half2 x = hin[srcidx(v) << 5];
            hacc = __hfma2(wrep(v), x, hacc);
        }
    }

    for (; j + 8 <= end; j += 8) {
        uint4 m0 = __ldcs(reinterpret_cast<const uint4*>(g_epk + j));
        uint4 m1 = __ldcs(reinterpret_cast<const uint4*>(g_epk + j + 4));
        if (act) {
            __half2 x0 = hin[srcidx(m0.x) << 5];
            __half2 x1 = hin[srcidx(m0.y) << 5];
            __half2 x2 = hin[srcidx(m0.z) << 5];
            __half2 x3 = hin[srcidx(m0.w) << 5];
            __half2 x4 = hin[srcidx(m1.x) << 5];
            __half2 x5 = hin[srcidx(m1.y) << 5];
            __half2 x6 = hin[srcidx(m1.z) << 5];
            __half2 x7 = hin[srcidx(m1.w) << 5];
            __half2 p0 = __hmul2(wrep(m0.x), x0);
            __half2 p1 = __hmul2(wrep(m0.y), x1);
            p0 = __hfma2(wrep(m0.z), x2, p0);
            p1 = __hfma2(wrep(m0.w), x3, p1);
            p0 = __hfma2(wrep(m1.x), x4, p0);
            p1 = __hfma2(wrep(m1.y), x5, p1);
            p0 = __hfma2(wrep(m1.z), x6, p0);
            p1 = __hfma2(wrep(m1.w), x7, p1);
            float2 f = __half22float2(__hadd2(p0, p1));
            accx += f.x;
            accy += f.y;
        }
    }
    for (; j < end; j++) {
        unsigned v = g_epk[j];
        if (act) {
            __half2 x = hin[srcidx(v) << 5];
            hacc = __hfma2(wrep(v), x, hacc);
        }
    }

    if (act) {
        float2 fr = __half22float2(hacc);
        accx += fr.x;
        accy += fr.y;

        hout[(size_t)gwarp * ROWP + lane] = __floats2half2_rn(accx, accy);

        float2 o;
        o.x = accx * Wm[(2 * lane) * NSTEP + s];
        o.y = accy * Wm[(2 * lane + 1) * NSTEP + s];
        float2* op = (float2*)(out + (size_t)gwarp * NCLS) + lane;
        float2 p = *op; o.x += p.x; o.y += p.y;
        *op = o;
    }
}

// ---------------- launch ------------------------------------------------------
extern "C" void kernel_launch(void* const* d_in, const int* in_sizes, int n_in,
                              void* d_out, int out_size) {
    const int*   ei     = (const int*)d_in[0];     // [2, E]
    const int*   row    = ei;
    const int*   col    = ei + N_EDGES;
    const float* attr   = (const float*)d_in[1];   // [E]
    const int*   target = (const int*)d_in[2];     // [N]
    const float* Wm     = (const float*)d_in[3];   // [C, S]
    float*       out    = (float*)d_out;           // [N, C]

    void* p_deg = nullptr; void* p_cnt = nullptr;
    cudaGetSymbolAddress(&p_deg, g_deg);
    cudaGetSymbolAddress(&p_cnt, g_cnt);
    cudaMemsetAsync(p_deg, 0, N_NODES * sizeof(float));
    cudaMemsetAsync(p_cnt, 0, N_NODES * sizeof(int));

    const int TB = 256;
    int nblk_edges = (N_EDGES + TB - 1) / TB;
    int nblk_warp  = (N_NODES + 7) / 8;    // 8 warps/block, 1 node/warp

    deg_kernel<<<nblk_edges, TB>>>(row, col, attr);            // launch 1
    scan_kernel<<<1, SCAN_B>>>();                              // launch 2
    fill_kernel<<<nblk_edges, TB>>>(row, col, attr);           // launch 3

    step1_kernel<<<PERS_BLOCKS, TB>>>(target, Wm, out);        // launch 4 (s=0)
    for (int s = 1; s < NSTEP; s++) {
        gather_kernel<<<nblk_warp, TB>>>(Wm, out, s);          // launches 5..13
    }
}

// round 11
// speedup vs baseline: 1.3111x; 1.0218x over previous
#include <cuda_runtime.h>
#include <cuda_fp16.h>

#define N_NODES 50000
#define N_EDGES 1600000
#define NCLS    48
#define NH2     24            // active half2 per row
#define ROWP    32            // padded half2 per row (128B rows)
#define NSTEP   10
#define SCAN_B  1024
#define CHUNK   49            // ceil(50000/1024)
#define PERS_BLOCKS 1216      // persistent grid for step1 only

// ---------------- device scratch (static, no runtime allocation) -------------
__device__ float   g_deg[N_NODES];
__device__ int     g_cnt[N_NODES];
__device__ int     g_off[N_NODES + 1];
__device__ int     g_cur[N_NODES];
__device__ __align__(16) unsigned g_epk[N_EDGES];    // (src<<16 | w_half_bits), CSR order
__device__ __half2 g_hh[2][(size_t)N_NODES * ROWP];  // fp16 feature buffers, 128B rows

static __device__ __forceinline__ __half2 wrep(unsigned v) {
    unsigned r = __byte_perm(v, v, 0x1010);
    __half2 h; *reinterpret_cast<unsigned*>(&h) = r; return h;
}
static __device__ __forceinline__ unsigned srcidx(unsigned v) { return v >> 16; }

// L2-only load of a half2 (bypass L1: no allocate/fill for zero-reuse data)
static __device__ __forceinline__ __half2 ldcg_h2(const __half2* p) {
    unsigned u = __ldcg(reinterpret_cast<const unsigned*>(p));
    __half2 h; *reinterpret_cast<unsigned*>(&h) = u; return h;
}

// ---------------- preprocessing ------------------------------------------------
__global__ void deg_kernel(const int* __restrict__ row, const int* __restrict__ col,
                           const float* __restrict__ attr) {
    int e = blockIdx.x * blockDim.x + threadIdx.x;
    if (e < N_EDGES) {
        atomicAdd(&g_deg[row[e]], attr[e]);
        atomicAdd(&g_cnt[col[e]], 1);
    }
}

// single-block exclusive scan of g_cnt -> g_off / g_cur (3-phase)
__global__ void scan_kernel() {
    __shared__ int sh[SCAN_B];
    int tid = threadIdx.x;
    int base = tid * CHUNK;

    int sum = 0;
    #pragma unroll 4
    for (int k = 0; k < CHUNK; k++) {
        int i = base + k;
        if (i < N_NODES) sum += g_cnt[i];
    }
    sh[tid] = sum;
    __syncthreads();
    for (int d = 1; d < SCAN_B; d <<= 1) {
        int t = (tid >= d) ? sh[tid - d] : 0;
        __syncthreads();
        sh[tid] += t;
        __syncthreads();
    }
    int run = sh[tid] - sum;
    #pragma unroll 4
    for (int k = 0; k < CHUNK; k++) {
        int i = base + k;
        if (i < N_NODES) {
            g_off[i] = run;
            g_cur[i] = run;
            run += g_cnt[i];
        }
    }
    if (tid == 0) g_off[N_NODES] = N_EDGES;
}

__global__ void fill_kernel(const int* __restrict__ row, const int* __restrict__ col,
                            const float* __restrict__ attr) {
    int e = blockIdx.x * blockDim.x + threadIdx.x;
    if (e < N_EDGES) {
        int r = row[e];
        int c = col[e];
        float w = attr[e] / fmaxf(g_deg[r], 1e-12f);
        unsigned wb = (unsigned)__half_as_ushort(__float2half_rn(w));
        int p = atomicAdd(&g_cur[c], 1);
        g_epk[p] = ((unsigned)r << 16) | wb;
    }
}

// ---------------- step 0: one-hot propagation via per-warp smem histogram ------
__global__ void __launch_bounds__(256)
step1_kernel(const int* __restrict__ target, const float* __restrict__ Wm,
             float* __restrict__ out) {
    __shared__ float hist[8][NCLS];
    int wip  = threadIdx.x >> 5;
    int lane = threadIdx.x & 31;
    float* h = hist[wip];

    int gw = (blockIdx.x * blockDim.x + threadIdx.x) >> 5;
    int nw = (gridDim.x * blockDim.x) >> 5;

    __half2* __restrict__ hout = g_hh[1];

    for (int n = gw; n < N_NODES; n += nw) {
        if (lane < NH2) { h[lane] = 0.f; h[lane + NH2] = 0.f; }
        __syncwarp();

        int beg = g_off[n];
        int end = g_off[n + 1];
        for (int j = beg + lane; j < end; j += 32) {
            unsigned v = g_epk[j];
            int c = target[v >> 16];
            float w = __half2float(__ushort_as_half((unsigned short)(v & 0xffffu)));
            atomicAdd(&h[c], w);
        }
        __syncwarp();

        if (lane < NH2) {
            float accx = h[2 * lane];
            float accy = h[2 * lane + 1];
            hout[(size_t)n * ROWP + lane] = __floats2half2_rn(accx, accy);
            float2 o;
            o.x = accx * Wm[(2 * lane) * NSTEP];       // s = 0
            o.y = accy * Wm[(2 * lane + 1) * NSTEP];
            float2* op = (float2*)(out + (size_t)n * NCLS) + lane;
            *op = o;                                    // overwrite poisoned out
        }
        __syncwarp();
    }
}

// ---------------- steps 1..9: one warp per node, L1-bypassed row gathers ------
__global__ void __launch_bounds__(256)
gather_kernel(const float* __restrict__ Wm, float* __restrict__ out, int s) {
    int gwarp = (blockIdx.x * blockDim.x + threadIdx.x) >> 5;
    int lane  = threadIdx.x & 31;
    if (gwarp >= N_NODES) return;

    const __half2* __restrict__ hin  = g_hh[s & 1] + lane;   // lane-offset base
    __half2*       __restrict__ hout = g_hh[(s & 1) ^ 1];

    int beg = g_off[gwarp];
    int end = g_off[gwarp + 1];
    bool act = (lane < NH2);

    float accx = 0.f, accy = 0.f;
    __half2 hacc = __floats2half2_rn(0.f, 0.f);

    int j = beg;
    // peel to 16B alignment of the packed metadata
    for (; j < end && (j & 3); j++) {
        unsigned v = g_epk[j];
        if (act) {
            __half2 x = ldcg_h2(hin + (srcidx(v) << 5));
            hacc = __hfma2(wrep(v), x, hacc);
        }
    }

    for (; j + 8 <= end; j += 8) {
        uint4 m0 = __ldcs(reinterpret_cast<const uint4*>(g_epk + j));
        uint4 m1 = __ldcs(reinterpret_cast<const uint4*>(g_epk + j + 4));
        if (act) {
            __half2 x0 = ldcg_h2(hin + (srcidx(m0.x) << 5));
            __half2 x1 = ldcg_h2(hin + (srcidx(m0.y) << 5));
            __half2 x2 = ldcg_h2(hin + (srcidx(m0.z) << 5));
            __half2 x3 = ldcg_h2(hin + (srcidx(m0.w) << 5));
            __half2 x4 = ldcg_h2(hin + (srcidx(m1.x) << 5));
            __half2 x5 = ldcg_h2(hin + (srcidx(m1.y) << 5));
            __half2 x6 = ldcg_h2(hin + (srcidx(m1.z) << 5));
            __half2 x7 = ldcg_h2(hin + (srcidx(m1.w) << 5));
            __half2 p0 = __hmul2(wrep(m0.x), x0);
            __half2 p1 = __hmul2(wrep(m0.y), x1);
            p0 = __hfma2(wrep(m0.z), x2, p0);
            p1 = __hfma2(wrep(m0.w), x3, p1);
            p0 = __hfma2(wrep(m1.x), x4, p0);
            p1 = __hfma2(wrep(m1.y), x5, p1);
            p0 = __hfma2(wrep(m1.z), x6, p0);
            p1 = __hfma2(wrep(m1.w), x7, p1);
            float2 f = __half22float2(__hadd2(p0, p1));
            accx += f.x;
            accy += f.y;
        }
    }
    for (; j < end; j++) {
        unsigned v = g_epk[j];
        if (act) {
            __half2 x = ldcg_h2(hin + (srcidx(v) << 5));
            hacc = __hfma2(wrep(v), x, hacc);
        }
    }

    if (act) {
        float2 fr = __half22float2(hacc);
        accx += fr.x;
        accy += fr.y;

        hout[(size_t)gwarp * ROWP + lane] = __floats2half2_rn(accx, accy);

        float2 o;
        o.x = accx * Wm[(2 * lane) * NSTEP + s];
        o.y = accy * Wm[(2 * lane + 1) * NSTEP + s];
        float2* op = (float2*)(out + (size_t)gwarp * NCLS) + lane;
        float2 p = *op; o.x += p.x; o.y += p.y;
        *op = o;
    }
}

// ---------------- launch ------------------------------------------------------
extern "C" void kernel_launch(void* const* d_in, const int* in_sizes, int n_in,
                              void* d_out, int out_size) {
    const int*   ei     = (const int*)d_in[0];     // [2, E]
    const int*   row    = ei;
    const int*   col    = ei + N_EDGES;
    const float* attr   = (const float*)d_in[1];   // [E]
    const int*   target = (const int*)d_in[2];     // [N]
    const float* Wm     = (const float*)d_in[3];   // [C, S]
    float*       out    = (float*)d_out;           // [N, C]

    void* p_deg = nullptr; void* p_cnt = nullptr;
    cudaGetSymbolAddress(&p_deg, g_deg);
    cudaGetSymbolAddress(&p_cnt, g_cnt);
    cudaMemsetAsync(p_deg, 0, N_NODES * sizeof(float));
    cudaMemsetAsync(p_cnt, 0, N_NODES * sizeof(int));

    const int TB = 256;
    int nblk_edges = (N_EDGES + TB - 1) / TB;
    int nblk_warp  = (N_NODES + 7) / 8;    // 8 warps/block, 1 node/warp

    deg_kernel<<<nblk_edges, TB>>>(row, col, attr);            // launch 1
    scan_kernel<<<1, SCAN_B>>>();                              // launch 2
    fill_kernel<<<nblk_edges, TB>>>(row, col, attr);           // launch 3

    step1_kernel<<<PERS_BLOCKS, TB>>>(target, Wm, out);        // launch 4 (s=0)
    for (int s = 1; s < NSTEP; s++) {
        gather_kernel<<<nblk_warp, TB>>>(Wm, out, s);          // launches 5..13
    }
}

// round 12
// speedup vs baseline: 1.3965x; 1.0652x over previous
#include <cuda_runtime.h>
#include <cuda_fp16.h>

#define N_NODES 50000
#define N_EDGES 1600000
#define NCLS    48
#define NH2     24            // active half2 per row
#define ROWP    32            // padded half2 per row (128B rows); 16 uint2
#define NSTEP   10
#define SCAN_B  1024
#define CHUNK   49            // ceil(50000/1024)
#define PERS_BLOCKS 1216      // persistent grid for step1 only

// ---------------- device scratch (static, no runtime allocation) -------------
__device__ float   g_deg[N_NODES];
__device__ int     g_cnt[N_NODES];
__device__ int     g_off[N_NODES + 1];
__device__ int     g_cur[N_NODES];
__device__ __align__(16) unsigned g_epk[N_EDGES];    // (src<<16 | w_half_bits), CSR order
__device__ __half2 g_hh[2][(size_t)N_NODES * ROWP];  // fp16 feature buffers, 128B rows

static __device__ __forceinline__ __half2 wrep(unsigned v) {
    unsigned r = __byte_perm(v, v, 0x1010);
    __half2 h; *reinterpret_cast<unsigned*>(&h) = r; return h;
}
static __device__ __forceinline__ __half2 u2h2(unsigned u) {
    __half2 h; *reinterpret_cast<unsigned*>(&h) = u; return h;
}

// L2-only 8B load (bypass L1 for zero-reuse gather traffic)
static __device__ __forceinline__ uint2 ldcg_u2(const uint2* p) {
    return __ldcg(p);
}

// ---------------- preprocessing ------------------------------------------------
__global__ void deg_kernel(const int* __restrict__ row, const int* __restrict__ col,
                           const float* __restrict__ attr) {
    int e = blockIdx.x * blockDim.x + threadIdx.x;
    if (e < N_EDGES) {
        atomicAdd(&g_deg[row[e]], attr[e]);
        atomicAdd(&g_cnt[col[e]], 1);
    }
}

// single-block exclusive scan of g_cnt -> g_off / g_cur (3-phase)
__global__ void scan_kernel() {
    __shared__ int sh[SCAN_B];
    int tid = threadIdx.x;
    int base = tid * CHUNK;

    int sum = 0;
    #pragma unroll 4
    for (int k = 0; k < CHUNK; k++) {
        int i = base + k;
        if (i < N_NODES) sum += g_cnt[i];
    }
    sh[tid] = sum;
    __syncthreads();
    for (int d = 1; d < SCAN_B; d <<= 1) {
        int t = (tid >= d) ? sh[tid - d] : 0;
        __syncthreads();
        sh[tid] += t;
        __syncthreads();
    }
    int run = sh[tid] - sum;
    #pragma unroll 4
    for (int k = 0; k < CHUNK; k++) {
        int i = base + k;
        if (i < N_NODES) {
            g_off[i] = run;
            g_cur[i] = run;
            run += g_cnt[i];
        }
    }
    if (tid == 0) g_off[N_NODES] = N_EDGES;
}

__global__ void fill_kernel(const int* __restrict__ row, const int* __restrict__ col,
                            const float* __restrict__ attr) {
    int e = blockIdx.x * blockDim.x + threadIdx.x;
    if (e < N_EDGES) {
        int r = row[e];
        int c = col[e];
        float w = attr[e] / fmaxf(g_deg[r], 1e-12f);
        unsigned wb = (unsigned)__half_as_ushort(__float2half_rn(w));
        int p = atomicAdd(&g_cur[c], 1);
        g_epk[p] = ((unsigned)r << 16) | wb;
    }
}

// ---------------- step 0: one-hot propagation via per-warp smem histogram ------
__global__ void __launch_bounds__(256)
step1_kernel(const int* __restrict__ target, const float* __restrict__ Wm,
             float* __restrict__ out) {
    __shared__ float hist[8][NCLS];
    int wip  = threadIdx.x >> 5;
    int lane = threadIdx.x & 31;
    float* h = hist[wip];

    int gw = (blockIdx.x * blockDim.x + threadIdx.x) >> 5;
    int nw = (gridDim.x * blockDim.x) >> 5;

    __half2* __restrict__ hout = g_hh[1];

    for (int n = gw; n < N_NODES; n += nw) {
        if (lane < NH2) { h[lane] = 0.f; h[lane + NH2] = 0.f; }
        __syncwarp();

        int beg = g_off[n];
        int end = g_off[n + 1];
        for (int j = beg + lane; j < end; j += 32) {
            unsigned v = g_epk[j];
            int c = target[v >> 16];
            float w = __half2float(__ushort_as_half((unsigned short)(v & 0xffffu)));
            atomicAdd(&h[c], w);
        }
        __syncwarp();

        if (lane < NH2) {
            float accx = h[2 * lane];
            float accy = h[2 * lane + 1];
            hout[(size_t)n * ROWP + lane] = __floats2half2_rn(accx, accy);
            float2 o;
            o.x = accx * Wm[(2 * lane) * NSTEP];       // s = 0
            o.y = accy * Wm[(2 * lane + 1) * NSTEP];
            float2* op = (float2*)(out + (size_t)n * NCLS) + lane;
            *op = o;                                    // overwrite poisoned out
        }
        __syncwarp();
    }
}

// ---------------- steps 1..9: paired-edge gather, 8B lane loads ---------------
// Two edges per LDG.64: lanes 0-11 fetch edge A's row, lanes 16-27 edge B's.
// Each lane owns 4 classes (uint2 = 2 half2). Cross-group combine via shfl.
__global__ void __launch_bounds__(256)
gather_kernel(const float* __restrict__ Wm, float* __restrict__ out, int s) {
    int gwarp = (blockIdx.x * blockDim.x + threadIdx.x) >> 5;
    int lane  = threadIdx.x & 31;
    if (gwarp >= N_NODES) return;

    int grp = lane >> 4;         // 0: lanes 0-15, 1: lanes 16-31
    int sub = lane & 15;         // class chunk index within row
    bool act = (sub < 12);       // 12 lanes x uint2 = 48 classes

    const uint2* __restrict__ hin_u2 =
        reinterpret_cast<const uint2*>(g_hh[s & 1]) + sub;    // lane-offset base
    __half2* __restrict__ hout = g_hh[(s & 1) ^ 1];

    int beg = g_off[gwarp];
    int end = g_off[gwarp + 1];

    float f0 = 0.f, f1 = 0.f, f2 = 0.f, f3 = 0.f;     // fp32 acc: classes 4sub..4sub+3
    __half2 q0 = __floats2half2_rn(0.f, 0.f);
    __half2 q1 = q0;

    int j = beg;
    // peel singles to 16B alignment (grp 0 only, avoids double count)
    for (; j < end && (j & 3); j++) {
        if (act && grp == 0) {
            unsigned v = g_epk[j];
            uint2 x = ldcg_u2(hin_u2 + ((size_t)(v >> 16) << 4));
            __half2 wh = wrep(v);
            q0 = __hfma2(wh, u2h2(x.x), q0);
            q1 = __hfma2(wh, u2h2(x.y), q1);
        }
    }

    for (; j + 8 <= end; j += 8) {
        uint4 m0 = __ldcs(reinterpret_cast<const uint4*>(g_epk + j));
        uint4 m1 = __ldcs(reinterpret_cast<const uint4*>(g_epk + j + 4));
        if (act) {
            __half2 p0, p1;
            {   // pair 1: edges (j, j+1)
                unsigned v = grp ? m0.y : m0.x;
                uint2 x = ldcg_u2(hin_u2 + ((size_t)(v >> 16) << 4));
                __half2 wh = wrep(v);
                p0 = __hmul2(wh, u2h2(x.x));
                p1 = __hmul2(wh, u2h2(x.y));
            }
            {   // pair 2: edges (j+2, j+3)
                unsigned v = grp ? m0.w : m0.z;
                uint2 x = ldcg_u2(hin_u2 + ((size_t)(v >> 16) << 4));
                __half2 wh = wrep(v);
                p0 = __hfma2(wh, u2h2(x.x), p0);
                p1 = __hfma2(wh, u2h2(x.y), p1);
            }
            {   // pair 3: edges (j+4, j+5)
                unsigned v = grp ? m1.y : m1.x;
                uint2 x = ldcg_u2(hin_u2 + ((size_t)(v >> 16) << 4));
                __half2 wh = wrep(v);
                p0 = __hfma2(wh, u2h2(x.x), p0);
                p1 = __hfma2(wh, u2h2(x.y), p1);
            }
            {   // pair 4: edges (j+6, j+7)
                unsigned v = grp ? m1.w : m1.z;
                uint2 x = ldcg_u2(hin_u2 + ((size_t)(v >> 16) << 4));
                __half2 wh = wrep(v);
                p0 = __hfma2(wh, u2h2(x.x), p0);
                p1 = __hfma2(wh, u2h2(x.y), p1);
            }
            float2 a = __half22float2(p0); f0 += a.x; f1 += a.y;
            float2 b = __half22float2(p1); f2 += b.x; f3 += b.y;
        }
    }
    // remainder pairs (j is 4-aligned here, so 8B meta loads are aligned)
    for (; j + 2 <= end; j += 2) {
        if (act) {
            uint2 mv = *reinterpret_cast<const uint2*>(g_epk + j);
            unsigned v = grp ? mv.y : mv.x;
            uint2 x = ldcg_u2(hin_u2 + ((size_t)(v >> 16) << 4));
            __half2 wh = wrep(v);
            q0 = __hfma2(wh, u2h2(x.x), q0);
            q1 = __hfma2(wh, u2h2(x.y), q1);
        }
    }
    // last single edge (grp 0 only)
    if (j < end && act && grp == 0) {
        unsigned v = g_epk[j];
        uint2 x = ldcg_u2(hin_u2 + ((size_t)(v >> 16) << 4));
        __half2 wh = wrep(v);
        q0 = __hfma2(wh, u2h2(x.x), q0);
        q1 = __hfma2(wh, u2h2(x.y), q1);
    }

    // promote leftover fp16 accumulators
    {
        float2 a = __half22float2(q0); f0 += a.x; f1 += a.y;
        float2 b = __half22float2(q1); f2 += b.x; f3 += b.y;
    }

    // combine the two edge-groups (lane l <-> l^16); all lanes participate
    f0 += __shfl_xor_sync(0xffffffffu, f0, 16);
    f1 += __shfl_xor_sync(0xffffffffu, f1, 16);
    f2 += __shfl_xor_sync(0xffffffffu, f2, 16);
    f3 += __shfl_xor_sync(0xffffffffu, f3, 16);

    if (act && grp == 0) {
        uint2 hv;
        __half2 h0 = __floats2half2_rn(f0, f1);
        __half2 h1 = __floats2half2_rn(f2, f3);
        hv.x = *reinterpret_cast<unsigned*>(&h0);
        hv.y = *reinterpret_cast<unsigned*>(&h1);
        reinterpret_cast<uint2*>(hout)[(size_t)gwarp * (ROWP / 2) + sub] = hv;

        int c = 4 * sub;
        float4* op = reinterpret_cast<float4*>(out + (size_t)gwarp * NCLS) + sub;
        float4 p = *op;
        float4 o;
        o.x = p.x + f0 * Wm[(c + 0) * NSTEP + s];
        o.y = p.y + f1 * Wm[(c + 1) * NSTEP + s];
        o.z = p.z + f2 * Wm[(c + 2) * NSTEP + s];
        o.w = p.w + f3 * Wm[(c + 3) * NSTEP + s];
        *op = o;
    }
}

// ---------------- launch ------------------------------------------------------
extern "C" void kernel_launch(void* const* d_in, const int* in_sizes, int n_in,
                              void* d_out, int out_size) {
    const int*   ei     = (const int*)d_in[0];     // [2, E]
    const int*   row    = ei;
    const int*   col    = ei + N_EDGES;
    const float* attr   = (const float*)d_in[1];   // [E]
    const int*   target = (const int*)d_in[2];     // [N]
    const float* Wm     = (const float*)d_in[3];   // [C, S]
    float*       out    = (float*)d_out;           // [N, C]

    void* p_deg = nullptr; void* p_cnt = nullptr;
    cudaGetSymbolAddress(&p_deg, g_deg);
    cudaGetSymbolAddress(&p_cnt, g_cnt);
    cudaMemsetAsync(p_deg, 0, N_NODES * sizeof(float));
    cudaMemsetAsync(p_cnt, 0, N_NODES * sizeof(int));

    const int TB = 256;
    int nblk_edges = (N_EDGES + TB - 1) / TB;
    int nblk_warp  = (N_NODES + 7) / 8;    // 8 warps/block, 1 node/warp

    deg_kernel<<<nblk_edges, TB>>>(row, col, attr);            // launch 1
    scan_kernel<<<1, SCAN_B>>>();                              // launch 2
    fill_kernel<<<nblk_edges, TB>>>(row, col, attr);           // launch 3

    step1_kernel<<<PERS_BLOCKS, TB>>>(target, Wm, out);        // launch 4 (s=0)
    for (int s = 1; s < NSTEP; s++) {
        gather_kernel<<<nblk_warp, TB>>>(Wm, out, s);          // launches 5..13
    }
}